// round 1
// baseline (speedup 1.0000x reference)
#include <cuda_runtime.h>
#include <cstdint>

#define NTOK 8192
#define DIM 256
#define EDIM 16
#define NCODE 8192
#define NSPLIT 16
#define NCHUNK (NCODE / NSPLIT)   // 512

__device__ int g_count;
__device__ int g_tokens[NTOK];
__device__ float4 g_proj4[NTOK * 4];          // [slot][16] floats
__device__ float g_logits[NCODE];
__device__ float g_lse;
__device__ unsigned long long g_key[NTOK];
__device__ double g_num;

__device__ __forceinline__ bool read_mask(const void* p, int i, int e4) {
    if (e4) return ((const int*)p)[i] != 0;       // also works for float32 bool (bits != 0)
    return ((const unsigned char*)p)[i] != 0;     // uint8 bool
}

// ---------------- Kernel A: init + mask-dtype detection + compaction ----------------
__global__ void k_init(const void* __restrict__ pad, const void* __restrict__ mm) {
    __shared__ int s_ni, s_nf;
    int tid = threadIdx.x;
    if (tid == 0) { s_ni = 0; s_nf = 0; g_count = 0; g_num = 0.0; }
    __syncthreads();

    // Detect encoding from first 8192 BYTES of masked_masks (safe for uint8 buffer).
    const unsigned* w = (const unsigned*)mm;
    int ni = 0, nf = 0;
    for (int i = tid; i < 2048; i += blockDim.x) {
        unsigned v = w[i];
        if (v != 0u && v != 1u) ni = 1;
        if (v != 0u && v != 0x3f800000u) nf = 1;
    }
    if (ni) atomicOr(&s_ni, 1);
    if (nf) atomicOr(&s_nf, 1);

    for (int i = tid; i < NTOK; i += blockDim.x) g_key[i] = ~0ull;
    __syncthreads();

    int e4 = (!s_ni || !s_nf) ? 1 : 0;   // 4-byte elements (int32 or float32), else 1-byte
    for (int t = tid; t < NTOK; t += blockDim.x) {
        if (read_mask(mm, t, e4) && read_mask(pad, t, e4)) {
            int pos = atomicAdd(&g_count, 1);
            g_tokens[pos] = t;
        }
    }
}

// ---------------- Kernel LNP: layernorm + 16-dim projection for masked tokens ----------------
__global__ void __launch_bounds__(256) k_lnproj(const float* __restrict__ xs,
                                                const float* __restrict__ gamma,
                                                const float* __restrict__ beta,
                                                const float* __restrict__ P) {
    __shared__ float s_g[DIM], s_b[DIM];
    __shared__ float s_P[DIM * EDIM];
    for (int i = threadIdx.x; i < DIM; i += blockDim.x) { s_g[i] = gamma[i]; s_b[i] = beta[i]; }
    for (int i = threadIdx.x; i < DIM * EDIM / 4; i += blockDim.x)
        ((float4*)s_P)[i] = ((const float4*)P)[i];
    __syncthreads();

    int slot = blockIdx.x * blockDim.x + threadIdx.x;
    if (slot >= g_count) return;
    int tok = g_tokens[slot];
    const float4* x4 = (const float4*)(xs + (size_t)tok * DIM);

    float sum = 0.f, sq = 0.f;
#pragma unroll 8
    for (int i = 0; i < DIM / 4; i++) {
        float4 v = x4[i];
        sum += (v.x + v.y) + (v.z + v.w);
        sq = fmaf(v.x, v.x, sq); sq = fmaf(v.y, v.y, sq);
        sq = fmaf(v.z, v.z, sq); sq = fmaf(v.w, v.w, sq);
    }
    float mu = sum * (1.f / DIM);
    float var = sq * (1.f / DIM) - mu * mu;
    float rstd = rsqrtf(var + 1e-5f);

    float proj[EDIM];
#pragma unroll
    for (int e = 0; e < EDIM; e++) proj[e] = 0.f;

#pragma unroll 4
    for (int i = 0; i < DIM / 4; i++) {
        float4 v = x4[i];
        float h0 = (v.x - mu) * rstd * s_g[4 * i + 0] + s_b[4 * i + 0];
        float h1 = (v.y - mu) * rstd * s_g[4 * i + 1] + s_b[4 * i + 1];
        float h2 = (v.z - mu) * rstd * s_g[4 * i + 2] + s_b[4 * i + 2];
        float h3 = (v.w - mu) * rstd * s_g[4 * i + 3] + s_b[4 * i + 3];
#pragma unroll
        for (int e = 0; e < EDIM; e++) {
            float a = fmaf(h0, s_P[(4 * i + 0) * EDIM + e],
                      fmaf(h1, s_P[(4 * i + 1) * EDIM + e], 0.f));
            float b = fmaf(h2, s_P[(4 * i + 2) * EDIM + e],
                      fmaf(h3, s_P[(4 * i + 3) * EDIM + e], 0.f));
            proj[e] += a + b;
        }
    }
    float4* out = &g_proj4[slot * 4];
    out[0] = make_float4(proj[0], proj[1], proj[2], proj[3]);
    out[1] = make_float4(proj[4], proj[5], proj[6], proj[7]);
    out[2] = make_float4(proj[8], proj[9], proj[10], proj[11]);
    out[3] = make_float4(proj[12], proj[13], proj[14], proj[15]);
}

// ---------------- Kernel B: constant logits L[n] = mask_emb . W[:,n] ----------------
__global__ void __launch_bounds__(256) k_logits(const float* __restrict__ W,
                                                const float* __restrict__ me) {
    __shared__ float s_me[DIM];
    for (int i = threadIdx.x; i < DIM; i += blockDim.x) s_me[i] = me[i];
    __syncthreads();
    int n = blockIdx.x * blockDim.x + threadIdx.x;
    float acc = 0.f;
#pragma unroll 8
    for (int d = 0; d < DIM; d++)
        acc = fmaf(s_me[d], W[(size_t)d * NCODE + n], acc);
    g_logits[n] = acc;
}

// ---------------- Kernel C: logsumexp of the 8192 constant logits ----------------
__global__ void __launch_bounds__(1024) k_lse() {
    __shared__ float red[32];
    int tid = threadIdx.x, lane = tid & 31, wid = tid >> 5;
    float m = -3.4e38f;
    for (int i = tid; i < NCODE; i += 1024) m = fmaxf(m, g_logits[i]);
#pragma unroll
    for (int off = 16; off; off >>= 1) m = fmaxf(m, __shfl_xor_sync(0xffffffffu, m, off));
    if (lane == 0) red[wid] = m;
    __syncthreads();
    if (wid == 0) {
        float v = red[lane];
#pragma unroll
        for (int off = 16; off; off >>= 1) v = fmaxf(v, __shfl_xor_sync(0xffffffffu, v, off));
        if (lane == 0) red[0] = v;
    }
    __syncthreads();
    float M = red[0];
    __syncthreads();
    float s = 0.f;
    for (int i = tid; i < NCODE; i += 1024) s += expf(g_logits[i] - M);
#pragma unroll
    for (int off = 16; off; off >>= 1) s += __shfl_xor_sync(0xffffffffu, s, off);
    if (lane == 0) red[wid] = s;
    __syncthreads();
    if (wid == 0) {
        float v = red[lane];
#pragma unroll
        for (int off = 16; off; off >>= 1) v += __shfl_xor_sync(0xffffffffu, v, off);
        if (lane == 0) g_lse = M + logf(v);
    }
}

// ---------------- Kernel D: per-masked-token argmin over codebook (split over N) ----------------
__global__ void __launch_bounds__(256) k_dist(const float* __restrict__ emb) {
    __shared__ float4 s_e[NCHUNK * 4];   // [i][16 floats]
    __shared__ float s_sq[NCHUNK];
    int tid = threadIdx.x;
    int nBase = blockIdx.y * NCHUNK;

    for (int i = tid; i < NCHUNK; i += 256) {
        int n = nBase + i;
        float v[16]; float sq = 0.f;
#pragma unroll
        for (int e = 0; e < 16; e++) { v[e] = emb[e * NCODE + n]; sq = fmaf(v[e], v[e], sq); }
        s_sq[i] = sq;
        s_e[i * 4 + 0] = make_float4(v[0], v[1], v[2], v[3]);
        s_e[i * 4 + 1] = make_float4(v[4], v[5], v[6], v[7]);
        s_e[i * 4 + 2] = make_float4(v[8], v[9], v[10], v[11]);
        s_e[i * 4 + 3] = make_float4(v[12], v[13], v[14], v[15]);
    }
    __syncthreads();

    int slot = blockIdx.x * 256 + tid;
    if (slot >= g_count) return;

    const float4* pr = &g_proj4[slot * 4];
    float4 p0 = pr[0], p1 = pr[1], p2 = pr[2], p3 = pr[3];

    float best = 3.4e38f;
    int bi = 0;
#pragma unroll 4
    for (int i = 0; i < NCHUNK; i++) {
        float4 a = s_e[i * 4 + 0];
        float4 b = s_e[i * 4 + 1];
        float4 c = s_e[i * 4 + 2];
        float4 d = s_e[i * 4 + 3];
        float s0 = fmaf(p0.x, a.x, fmaf(p0.y, a.y, fmaf(p0.z, a.z, p0.w * a.w)));
        float s1 = fmaf(p1.x, b.x, fmaf(p1.y, b.y, fmaf(p1.z, b.z, p1.w * b.w)));
        float s2 = fmaf(p2.x, c.x, fmaf(p2.y, c.y, fmaf(p2.z, c.z, p2.w * c.w)));
        float s3 = fmaf(p3.x, d.x, fmaf(p3.y, d.y, fmaf(p3.z, d.z, p3.w * d.w)));
        float s = (s0 + s1) + (s2 + s3);
        float sc = fmaf(-2.f, s, s_sq[i]);      // embsq[n] - 2*proj.emb  (proj^2 const, dropped)
        if (sc < best) { best = sc; bi = i; }
    }
    int bn = nBase + bi;
    unsigned ub = __float_as_uint(best);
    unsigned mk = (ub & 0x80000000u) ? ~ub : (ub | 0x80000000u);  // order-preserving float->uint
    unsigned long long key = (((unsigned long long)mk) << 32) | (unsigned)bn;
    atomicMin(&g_key[slot], key);
}

// ---------------- Kernel E: ce sum over masked tokens ----------------
__global__ void __launch_bounds__(256) k_ce() {
    int slot = blockIdx.x * blockDim.x + threadIdx.x;
    float ce = 0.f;
    if (slot < g_count) {
        unsigned n = (unsigned)(g_key[slot] & 0xffffffffu);
        ce = g_lse - g_logits[n];
    }
#pragma unroll
    for (int off = 16; off; off >>= 1) ce += __shfl_xor_sync(0xffffffffu, ce, off);
    __shared__ float red[8];
    if ((threadIdx.x & 31) == 0) red[threadIdx.x >> 5] = ce;
    __syncthreads();
    if (threadIdx.x == 0) {
        float s = 0.f;
#pragma unroll
        for (int i = 0; i < 8; i++) s += red[i];
        atomicAdd(&g_num, (double)s);
    }
}

// ---------------- Kernel F: finalize ----------------
__global__ void k_fin(float* __restrict__ out, int n) {
    double v = g_num / (double)g_count;   // C == 1
    int i = blockIdx.x * blockDim.x + threadIdx.x;
    if (i < n) out[i] = (float)v;
}

extern "C" void kernel_launch(void* const* d_in, const int* in_sizes, int n_in,
                              void* d_out, int out_size) {
    (void)in_sizes; (void)n_in;
    const float* xs    = (const float*)d_in[0];
    const void*  pad   = d_in[1];
    const void*  mm    = d_in[2];
    const float* gamma = (const float*)d_in[3];
    const float* beta  = (const float*)d_in[4];
    const float* P     = (const float*)d_in[5];
    const float* emb   = (const float*)d_in[6];   // (1,16,8192)
    const float* W     = (const float*)d_in[7];   // (1,256,8192)
    const float* me    = (const float*)d_in[8];

    k_init<<<1, 1024>>>(pad, mm);
    k_lnproj<<<NTOK / 256, 256>>>(xs, gamma, beta, P);
    k_logits<<<NCODE / 256, 256>>>(W, me);
    k_lse<<<1, 1024>>>();
    dim3 gd(NTOK / 256, NSPLIT);
    k_dist<<<gd, 256>>>(emb);
    k_ce<<<NTOK / 256, 256>>>();
    k_fin<<<(out_size + 255) / 256, 256>>>((float*)d_out, out_size);
}

// round 2
// speedup vs baseline: 1.5575x; 1.5575x over previous
#include <cuda_runtime.h>
#include <cstdint>

#define NTOK 8192
#define DIM 256
#define EDIM 16
#define NCODE 8192
#define CHUNK 128           // codes per dist block
#define NSPLIT (NCODE / CHUNK)   // 64
#define TOKS_PER_DBLK 512   // 256 threads x 2 tokens

typedef unsigned long long ull;

__device__ int g_count;                 // zero-init; reset by k_fin each run
__device__ float4 g_proj4[NTOK * 4];    // [slot][16] floats
__device__ float g_logits[NCODE];
__device__ ull g_key[NTOK];

__device__ __forceinline__ bool read_mask(const void* p, int i, int e4) {
    if (e4) return ((const int*)p)[i] != 0;       // int32 / float32 bool (bits != 0)
    return ((const unsigned char*)p)[i] != 0;     // uint8 bool
}

__device__ __forceinline__ ull pk2(float lo, float hi) {
    ull r;
    asm("mov.b64 %0, {%1, %2};" : "=l"(r) : "f"(lo), "f"(hi));
    return r;
}
__device__ __forceinline__ ull ffma2(ull a, ull b, ull c) {
    ull d;
    asm("fma.rn.f32x2 %0, %1, %2, %3;" : "=l"(d) : "l"(a), "l"(b), "l"(c));
    return d;
}
__device__ __forceinline__ ull fadd2(ull a, ull b) {
    ull d;
    asm("add.rn.f32x2 %0, %1, %2;" : "=l"(d) : "l"(a), "l"(b));
    return d;
}

// ================= Kernel 1: block-specialized front =================
// blocks [0,64):  LN + 16-dim projection for ALL tokens (2 threads per token,
//                 D split), compaction of masked tokens via ballot+scan+atomic.
// blocks [64,96): constant logits L[n] = mask_emb . W[:,n]
__global__ void __launch_bounds__(256) k_front(const float* __restrict__ xs,
                                               const void* __restrict__ pad,
                                               const void* __restrict__ mm,
                                               const float* __restrict__ gamma,
                                               const float* __restrict__ beta,
                                               const float* __restrict__ P,
                                               const float* __restrict__ W,
                                               const float* __restrict__ me) {
    int tid = threadIdx.x;
    int bx = blockIdx.x;

    if (bx >= 64) {
        // ---- logits branch ----
        __shared__ float s_me[DIM];
        for (int i = tid; i < DIM; i += 256) s_me[i] = me[i];
        __syncthreads();
        int n = (bx - 64) * 256 + tid;
        float acc = 0.f;
#pragma unroll 8
        for (int d = 0; d < DIM; d++)
            acc = fmaf(s_me[d], __ldg(&W[(size_t)d * NCODE + n]), acc);
        g_logits[n] = acc;
        return;
    }

    // ---- LN + proj branch ----
    __shared__ float s_P[DIM * EDIM];
    __shared__ float s_g[DIM], s_b[DIM];
    __shared__ int s_wb[8];
    __shared__ int s_base;
    __shared__ int s_det;

    if (tid == 0) s_det = 0;
    for (int i = tid; i < DIM; i += 256) { s_g[i] = gamma[i]; s_b[i] = beta[i]; }
    for (int i = tid; i < DIM * EDIM / 4; i += 256)
        ((float4*)s_P)[i] = ((const float4*)P)[i];
    __syncthreads();

    // mask dtype detection (first 8192 bytes of masked_masks)
    {
        const unsigned* w = (const unsigned*)mm;
        int ni = 0, nf = 0;
        for (int i = tid; i < 2048; i += 256) {
            unsigned v = w[i];
            if (v != 0u && v != 1u) ni = 1;
            if (v != 0u && v != 0x3f800000u) nf = 1;
        }
        int fl = (ni ? 1 : 0) | (nf ? 2 : 0);
        if (fl) atomicOr(&s_det, fl);
    }
    __syncthreads();
    int e4 = (((s_det & 1) == 0) || ((s_det & 2) == 0)) ? 1 : 0;

    int tok = bx * 128 + (tid >> 1);      // 2 threads per token
    int half = tid & 1;
    bool m = read_mask(mm, tok, e4) && read_mask(pad, tok, e4);

    // compaction (even lanes register the slot)
    int lane = tid & 31, wid = tid >> 5;
    unsigned bal = __ballot_sync(0xffffffffu, m);
    unsigned evens = bal & 0x55555555u;
    int wcount = __popc(evens);
    int prefix = __popc(evens & ((1u << lane) - 1));
    if (lane == 0) s_wb[wid] = wcount;
    __syncthreads();
    if (tid == 0) {
        int tot = 0;
#pragma unroll
        for (int i = 0; i < 8; i++) { int c = s_wb[i]; s_wb[i] = tot; tot += c; }
        s_base = atomicAdd(&g_count, tot);
    }
    __syncthreads();
    int slot = s_base + s_wb[wid] + prefix;

    // LN stats over my 128-element half
    const float4* x4 = (const float4*)(xs + (size_t)tok * DIM + half * 128);
    float sum = 0.f, sq = 0.f;
#pragma unroll 8
    for (int i = 0; i < 32; i++) {
        float4 v = x4[i];
        sum += (v.x + v.y) + (v.z + v.w);
        sq = fmaf(v.x, v.x, sq); sq = fmaf(v.y, v.y, sq);
        sq = fmaf(v.z, v.z, sq); sq = fmaf(v.w, v.w, sq);
    }
    sum += __shfl_xor_sync(0xffffffffu, sum, 1);
    sq  += __shfl_xor_sync(0xffffffffu, sq, 1);
    float mu = sum * (1.f / DIM);
    float var = sq * (1.f / DIM) - mu * mu;
    float rstd = rsqrtf(var + 1e-5f);

    // projection partial over my D half
    float proj[EDIM];
#pragma unroll
    for (int e = 0; e < EDIM; e++) proj[e] = 0.f;
    int dbase = half * 128;
#pragma unroll 4
    for (int i = 0; i < 32; i++) {
        float4 v = x4[i];
        int d = dbase + 4 * i;
        float h0 = (v.x - mu) * rstd * s_g[d + 0] + s_b[d + 0];
        float h1 = (v.y - mu) * rstd * s_g[d + 1] + s_b[d + 1];
        float h2 = (v.z - mu) * rstd * s_g[d + 2] + s_b[d + 2];
        float h3 = (v.w - mu) * rstd * s_g[d + 3] + s_b[d + 3];
#pragma unroll
        for (int e = 0; e < EDIM; e++) {
            float a = fmaf(h0, s_P[(d + 0) * EDIM + e],
                      fmaf(h1, s_P[(d + 1) * EDIM + e], 0.f));
            float b = fmaf(h2, s_P[(d + 2) * EDIM + e],
                      fmaf(h3, s_P[(d + 3) * EDIM + e], 0.f));
            proj[e] += a + b;
        }
    }
    // combine partner halves
#pragma unroll
    for (int e = 0; e < EDIM; e++)
        proj[e] += __shfl_xor_sync(0xffffffffu, proj[e], 1);

    if (m && half == 0) {
        float4* out = &g_proj4[slot * 4];
        out[0] = make_float4(proj[0], proj[1], proj[2], proj[3]);
        out[1] = make_float4(proj[4], proj[5], proj[6], proj[7]);
        out[2] = make_float4(proj[8], proj[9], proj[10], proj[11]);
        out[3] = make_float4(proj[12], proj[13], proj[14], proj[15]);
        g_key[slot] = ~0ull;
    }
}

// ================= Kernel 2: argmin over codebook (FFMA2, 2 tokens/thread) ====
__global__ void __launch_bounds__(256) k_dist(const float* __restrict__ emb) {
    int cnt = g_count;
    int tbase = blockIdx.x * TOKS_PER_DBLK;
    if (tbase >= cnt) return;

    __shared__ float s_ed[CHUNK * 32];   // each code: 16 values duplicated
    __shared__ float s_sq[CHUNK * 2];    // |emb|^2 duplicated
    int tid = threadIdx.x;
    int nb = blockIdx.y * CHUNK;

    if (tid < CHUNK) {
        int n = nb + tid;
        float v[16]; float sq = 0.f;
#pragma unroll
        for (int e = 0; e < 16; e++) { v[e] = __ldg(&emb[e * NCODE + n]); sq = fmaf(v[e], v[e], sq); }
        float2* dd = (float2*)&s_ed[tid * 32];
#pragma unroll
        for (int e = 0; e < 16; e++) dd[e] = make_float2(v[e], v[e]);
        s_sq[2 * tid] = sq; s_sq[2 * tid + 1] = sq;
    }
    __syncthreads();

    int s0 = tbase + tid * 2;
    // packed proj pairs: lo = token s0, hi = token s0+1
    const float* pa = (const float*)&g_proj4[s0 * 4];
    const float* pb = (const float*)&g_proj4[(s0 + 1) * 4];
    float4 A0 = ((const float4*)pa)[0], A1 = ((const float4*)pa)[1];
    float4 A2 = ((const float4*)pa)[2], A3 = ((const float4*)pa)[3];
    float4 B0 = ((const float4*)pb)[0], B1 = ((const float4*)pb)[1];
    float4 B2 = ((const float4*)pb)[2], B3 = ((const float4*)pb)[3];
    ull pp[16];
    pp[0]=pk2(A0.x,B0.x); pp[1]=pk2(A0.y,B0.y); pp[2]=pk2(A0.z,B0.z); pp[3]=pk2(A0.w,B0.w);
    pp[4]=pk2(A1.x,B1.x); pp[5]=pk2(A1.y,B1.y); pp[6]=pk2(A1.z,B1.z); pp[7]=pk2(A1.w,B1.w);
    pp[8]=pk2(A2.x,B2.x); pp[9]=pk2(A2.y,B2.y); pp[10]=pk2(A2.z,B2.z); pp[11]=pk2(A2.w,B2.w);
    pp[12]=pk2(A3.x,B3.x); pp[13]=pk2(A3.y,B3.y); pp[14]=pk2(A3.z,B3.z); pp[15]=pk2(A3.w,B3.w);

    const ull NEG2 = 0xC0000000C0000000ull;  // (-2.f, -2.f)
    float best0 = 3.4e38f, best1 = 3.4e38f;
    int b0 = 0, b1 = 0;

#pragma unroll 2
    for (int i = 0; i < CHUNK; i++) {
        const longlong2* r8 = (const longlong2*)(s_ed + i * 32);
        ull acca = 0ull, accb = 0ull;
#pragma unroll
        for (int k = 0; k < 4; k++) {
            longlong2 q = r8[k];
            acca = ffma2(pp[2 * k], (ull)q.x, acca);
            acca = ffma2(pp[2 * k + 1], (ull)q.y, acca);
        }
#pragma unroll
        for (int k = 4; k < 8; k++) {
            longlong2 q = r8[k];
            accb = ffma2(pp[2 * k], (ull)q.x, accb);
            accb = ffma2(pp[2 * k + 1], (ull)q.y, accb);
        }
        ull acc = fadd2(acca, accb);
        ull sq2 = *(const ull*)(s_sq + 2 * i);
        ull sc2 = ffma2(acc, NEG2, sq2);   // sq - 2*dot (|proj|^2 const, dropped)
        float f0 = __uint_as_float((unsigned)sc2);
        float f1 = __uint_as_float((unsigned)(sc2 >> 32));
        if (f0 < best0) { best0 = f0; b0 = i; }
        if (f1 < best1) { best1 = f1; b1 = i; }
    }

    if (s0 < cnt) {
        unsigned ub = __float_as_uint(best0);
        unsigned mk = (ub & 0x80000000u) ? ~ub : (ub | 0x80000000u);
        atomicMin(&g_key[s0], (((ull)mk) << 32) | (unsigned)(nb + b0));
    }
    if (s0 + 1 < cnt) {
        unsigned ub = __float_as_uint(best1);
        unsigned mk = (ub & 0x80000000u) ? ~ub : (ub | 0x80000000u);
        atomicMin(&g_key[s0 + 1], (((ull)mk) << 32) | (unsigned)(nb + b1));
    }
}

// ================= Kernel 3: lse + CE sum + finalize + reset =================
__global__ void __launch_bounds__(1024) k_fin(float* __restrict__ out, int n) {
    __shared__ float redf[32];
    __shared__ double redd[32];
    __shared__ float s_bc;
    int tid = threadIdx.x, lane = tid & 31, wid = tid >> 5;
    int cnt = g_count;

    // pass 1: max of logits
    float m = -3.4e38f;
#pragma unroll
    for (int i = tid; i < NCODE; i += 1024) m = fmaxf(m, g_logits[i]);
#pragma unroll
    for (int o = 16; o; o >>= 1) m = fmaxf(m, __shfl_xor_sync(0xffffffffu, m, o));
    if (lane == 0) redf[wid] = m;
    __syncthreads();
    if (wid == 0) {
        float v = redf[lane];
#pragma unroll
        for (int o = 16; o; o >>= 1) v = fmaxf(v, __shfl_xor_sync(0xffffffffu, v, o));
        if (lane == 0) s_bc = v;
    }
    __syncthreads();
    float M = s_bc;
    __syncthreads();

    // pass 2: sum exp
    float s = 0.f;
#pragma unroll
    for (int i = tid; i < NCODE; i += 1024) s += expf(g_logits[i] - M);
#pragma unroll
    for (int o = 16; o; o >>= 1) s += __shfl_xor_sync(0xffffffffu, s, o);
    if (lane == 0) redf[wid] = s;
    __syncthreads();
    if (wid == 0) {
        float v = redf[lane];
#pragma unroll
        for (int o = 16; o; o >>= 1) v += __shfl_xor_sync(0xffffffffu, v, o);
        if (lane == 0) s_bc = M + logf(v);
    }
    __syncthreads();
    float lse = s_bc;

    // pass 3: sum of L[target] over masked slots
    double acc = 0.0;
    for (int slot = tid; slot < cnt; slot += 1024) {
        unsigned nidx = (unsigned)(g_key[slot] & 0xffffffffu);
        acc += (double)g_logits[nidx];
    }
#pragma unroll
    for (int o = 16; o; o >>= 1) acc += __shfl_xor_sync(0xffffffffu, acc, o);
    if (lane == 0) redd[wid] = acc;
    __syncthreads();
    if (tid == 0) {
        double t = 0.0;
#pragma unroll
        for (int i = 0; i < 32; i++) t += redd[i];
        float loss = (float)((double)lse - t / (double)cnt);   // C == 1
        for (int i = 0; i < n; i++) out[i] = loss;
        g_count = 0;   // reset for next graph replay
    }
}

extern "C" void kernel_launch(void* const* d_in, const int* in_sizes, int n_in,
                              void* d_out, int out_size) {
    (void)in_sizes; (void)n_in;
    const float* xs    = (const float*)d_in[0];
    const void*  pad   = d_in[1];
    const void*  mm    = d_in[2];
    const float* gamma = (const float*)d_in[3];
    const float* beta  = (const float*)d_in[4];
    const float* P     = (const float*)d_in[5];
    const float* emb   = (const float*)d_in[6];   // (1,16,8192)
    const float* W     = (const float*)d_in[7];   // (1,256,8192)
    const float* me    = (const float*)d_in[8];

    k_front<<<96, 256>>>(xs, pad, mm, gamma, beta, P, W, me);
    dim3 gd(NTOK / TOKS_PER_DBLK, NSPLIT);        // 16 x 64
    k_dist<<<gd, 256>>>(emb);
    k_fin<<<1, 1024>>>((float*)d_out, out_size);
}